// round 6
// baseline (speedup 1.0000x reference)
#include <cuda_runtime.h>

// CreateOverlappingWindows: x (B=64, T=2000, C=26) fp32 ->
// out (B*T, 19*26), N_CONTEXT=9, zero-padded edges.
//
// out row (b,t) = contiguous x slice x[b, t-9 : t+10, :] flattened.
// Direct gather: 4x predicated LDG.64 -> 1x STG.256 (st.global.cs.v8.f32,
// Blackwell 256-bit store), flat fully-coalesced streaming stores.
//
// TILE_T=40: tile base offset (b*2000+t0)*494 is divisible by 8 floats
// (t0 mult of 4 -> t0*494 % 8 == 0; 2000*494 % 8 == 0), so every 8-float
// chunk is 32B-aligned.
//
// For chunk base fe (fe % 8 == 0): trow = fe/494 (one divide), k0 = fe -
// trow*494. Half j (j=0..3) covers floats fe+2j; it belongs to row
// trow + (k0+2j >= 494). Source p_j = s0 + fe + 2j - trow_j*468,
// valid iff (unsigned)p_j < 52000.

#define B_DIM   64
#define T_DIM   2000
#define C_DIM   26
#define NCTX    9
#define WINDOW  19
#define ROW_F   (WINDOW * C_DIM)          // 494
#define SLIDE   (ROW_F - C_DIM)           // 468
#define XROW_F  (T_DIM * C_DIM)           // 52000 floats per batch
#define TILE_T  40                         // output rows per block
#define TILE_F8 (TILE_T * ROW_F / 8)       // 2470 v8-chunks per tile
#define NTHREADS 256

__global__ __launch_bounds__(NTHREADS) void overlap_windows_kernel(
    const float* __restrict__ x, float* __restrict__ out)
{
    const int tile = blockIdx.x;          // 0..49
    const int b    = blockIdx.y;          // 0..63
    const int t0   = tile * TILE_T;
    const int tid  = threadIdx.x;

    const float* xb = x + (size_t)b * XROW_F;
    float* tout = out + ((size_t)b * T_DIM + t0) * ROW_F;  // 32B aligned
    const int s0 = (t0 - NCTX) * C_DIM;   // may be negative (tile 0)

    #pragma unroll 2
    for (int i8 = tid; i8 < TILE_F8; i8 += NTHREADS) {
        const int fe   = i8 * 8;
        const int trow = fe / ROW_F;                  // mul-hi divide
        const int k0   = fe - trow * ROW_F;           // 0..492, even

        float2 h[4];
        #pragma unroll
        for (int j = 0; j < 4; j++) {
            const int cross = (k0 + 2 * j >= ROW_F) ? 1 : 0;
            const int p = s0 + fe + 2 * j - (trow + cross) * SLIDE;
            h[j] = make_float2(0.0f, 0.0f);
            if ((unsigned)p < (unsigned)XROW_F)
                h[j] = *reinterpret_cast<const float2*>(xb + p);
        }

        asm volatile(
            "st.global.cs.v8.f32 [%0], {%1,%2,%3,%4,%5,%6,%7,%8};"
            :: "l"(tout + fe),
               "f"(h[0].x), "f"(h[0].y), "f"(h[1].x), "f"(h[1].y),
               "f"(h[2].x), "f"(h[2].y), "f"(h[3].x), "f"(h[3].y)
            : "memory");
    }
}

extern "C" void kernel_launch(void* const* d_in, const int* in_sizes, int n_in,
                              void* d_out, int out_size)
{
    const float* x = (const float*)d_in[0];
    float* out = (float*)d_out;

    dim3 grid(T_DIM / TILE_T, B_DIM);     // 50 x 64 = 3200 blocks
    overlap_windows_kernel<<<grid, NTHREADS>>>(x, out);
}

// round 7
// speedup vs baseline: 1.0019x; 1.0019x over previous
#include <cuda_runtime.h>

// CreateOverlappingWindows: x (B=64, T=2000, C=26) fp32 ->
// out (B*T, 19*26), N_CONTEXT=9, zero-padded edges.
//
// out row (b,t) = contiguous x slice x[b, t-9 : t+10, :] flattened.
// Direct gather: 2x predicated LDG.64 -> 1x STG.128, flat fully-coalesced
// stores with DEFAULT cache policy (no .cs: let L2 batch writebacks).
//
// src for flat tile offset fe: trow = fe/494, p = s0 + fe - trow*468,
// valid iff (unsigned)p < 52000.

#define B_DIM   64
#define T_DIM   2000
#define C_DIM   26
#define NCTX    9
#define WINDOW  19
#define ROW_F   (WINDOW * C_DIM)          // 494
#define SLIDE   (ROW_F - C_DIM)           // 468
#define XROW_F  (T_DIM * C_DIM)           // 52000 floats per batch
#define TILE_T  50                         // output rows per block
#define TILE_F4 (TILE_T * ROW_F / 4)       // 6175 float4 per tile
#define NTHREADS 256

__global__ __launch_bounds__(NTHREADS) void overlap_windows_kernel(
    const float* __restrict__ x, float* __restrict__ out)
{
    const int tile = blockIdx.x;          // 0..39
    const int b    = blockIdx.y;          // 0..63
    const int t0   = tile * TILE_T;
    const int tid  = threadIdx.x;

    const float* xb = x + (size_t)b * XROW_F;
    float* tout = out + ((size_t)b * T_DIM + t0) * ROW_F;  // 16B aligned
    const int s0 = (t0 - NCTX) * C_DIM;   // may be negative (tile 0)

    #pragma unroll 8
    for (int i4 = tid; i4 < TILE_F4; i4 += NTHREADS) {
        const int fe = i4 * 4;

        // first float2 half
        const int trow0 = fe / ROW_F;                 // mul-hi divide
        const int k0    = fe - trow0 * ROW_F;         // 0..492, even
        const int p0    = s0 + fe - trow0 * SLIDE;
        // second half: crosses into next output row iff k0+2 >= 494
        const int trow1 = trow0 + ((k0 + 2 >= ROW_F) ? 1 : 0);
        const int p1    = s0 + (fe + 2) - trow1 * SLIDE;

        float2 a = make_float2(0.0f, 0.0f);
        float2 c = make_float2(0.0f, 0.0f);
        if ((unsigned)p0 < (unsigned)XROW_F)
            a = *reinterpret_cast<const float2*>(xb + p0);
        if ((unsigned)p1 < (unsigned)XROW_F)
            c = *reinterpret_cast<const float2*>(xb + p1);

        *reinterpret_cast<float4*>(tout + fe) = make_float4(a.x, a.y, c.x, c.y);
    }
}

extern "C" void kernel_launch(void* const* d_in, const int* in_sizes, int n_in,
                              void* d_out, int out_size)
{
    const float* x = (const float*)d_in[0];
    float* out = (float*)d_out;

    dim3 grid(T_DIM / TILE_T, B_DIM);     // 40 x 64 = 2560 blocks
    overlap_windows_kernel<<<grid, NTHREADS>>>(x, out);
}

// round 8
// speedup vs baseline: 1.0137x; 1.0117x over previous
#include <cuda_runtime.h>
#include <cstdint>

// CreateOverlappingWindows: x (B=64, T=2000, C=26) fp32 ->
// out (B*T, 19*26), N_CONTEXT=9, zero-padded edges.
//
// Gather into smem (STS.128), then TMA bulk-store (cp.async.bulk 1D) the
// flat-contiguous tile to global. Two half-tiles pipeline compute vs TMA.
//
// src for flat tile offset fe: trow = fe/494, p = s0 + fe - trow*468,
// valid iff (unsigned)p < 52000.

#define B_DIM    64
#define T_DIM    2000
#define C_DIM    26
#define NCTX     9
#define WINDOW   19
#define ROW_F    (WINDOW * C_DIM)         // 494
#define SLIDE    (ROW_F - C_DIM)          // 468
#define XROW_F   (T_DIM * C_DIM)          // 52000 floats per batch
#define TILE_T   20                        // output rows per block (even -> 16B-aligned base)
#define TILE_F   (TILE_T * ROW_F)          // 9880 floats
#define HALF_F   (TILE_F / 2)              // 4940 floats
#define HALF_F4  (HALF_F / 4)              // 1235 float4
#define HALF_B   (HALF_F * 4)              // 19760 bytes (mult of 16)
#define NTHREADS 256

__global__ __launch_bounds__(NTHREADS) void overlap_windows_kernel(
    const float* __restrict__ x, float* __restrict__ out)
{
    __shared__ __align__(16) float sm[TILE_F];

    const int tile = blockIdx.x;          // 0..99
    const int b    = blockIdx.y;          // 0..63
    const int t0   = tile * TILE_T;
    const int tid  = threadIdx.x;

    const float* xb = x + (size_t)b * XROW_F;
    float* tout = out + ((size_t)b * T_DIM + t0) * ROW_F;  // 16B aligned
    const int s0 = (t0 - NCTX) * C_DIM;

    uint32_t sm_u32;
    asm("{ .reg .u64 t; cvta.to.shared.u64 t, %1; cvt.u32.u64 %0, t; }"
        : "=r"(sm_u32) : "l"(sm));

    #pragma unroll
    for (int half = 0; half < 2; half++) {
        const int fbase = half * HALF_F;

        #pragma unroll 5
        for (int i4 = tid; i4 < HALF_F4; i4 += NTHREADS) {
            const int fe = fbase + i4 * 4;

            const int trow0 = fe / ROW_F;                 // mul-hi divide
            const int k0    = fe - trow0 * ROW_F;
            const int p0    = s0 + fe - trow0 * SLIDE;
            const int trow1 = trow0 + ((k0 + 2 >= ROW_F) ? 1 : 0);
            const int p1    = s0 + (fe + 2) - trow1 * SLIDE;

            float2 a = make_float2(0.0f, 0.0f);
            float2 c = make_float2(0.0f, 0.0f);
            if ((unsigned)p0 < (unsigned)XROW_F)
                a = *reinterpret_cast<const float2*>(xb + p0);
            if ((unsigned)p1 < (unsigned)XROW_F)
                c = *reinterpret_cast<const float2*>(xb + p1);

            *reinterpret_cast<float4*>(sm + fe) = make_float4(a.x, a.y, c.x, c.y);
        }
        __syncthreads();

        if (tid == 0) {
            asm volatile("fence.proxy.async.shared::cta;" ::: "memory");
            asm volatile(
                "cp.async.bulk.global.shared::cta.bulk_group [%0], [%1], %2;"
                :: "l"(tout + fbase), "r"(sm_u32 + fbase * 4), "r"(HALF_B)
                : "memory");
            asm volatile("cp.async.bulk.commit_group;" ::: "memory");
        }
        // next half writes the other smem region; no wait needed here
    }

    __syncthreads();
    if (tid == 0) {
        asm volatile("cp.async.bulk.wait_group 0;" ::: "memory");
    }
    __syncthreads();   // hold all threads until TMA has drained smem
}

extern "C" void kernel_launch(void* const* d_in, const int* in_sizes, int n_in,
                              void* d_out, int out_size)
{
    const float* x = (const float*)d_in[0];
    float* out = (float*)d_out;

    dim3 grid(T_DIM / TILE_T, B_DIM);     // 100 x 64 = 6400 blocks
    overlap_windows_kernel<<<grid, NTHREADS>>>(x, out);
}

// round 9
// speedup vs baseline: 1.1072x; 1.0923x over previous
#include <cuda_runtime.h>

// CreateOverlappingWindows: x (B=64, T=2000, C=26) fp32 ->
// out (B*T, 19*26), N_CONTEXT=9, zero-padded edges.
//
// out row (b,t) = contiguous x slice x[b, t-9 : t+10, :] flattened.
// Direct gather: 2x predicated LDG.64 (L2-resident source) -> 1x STG.128
// streaming (.cs). Established plateau is the HBM *write* roofline
// (~5.8 TB/s for 253 MB/replay); this round only perturbs DRAM-side
// scheduling: grid ordered so concurrent CTAs write to different batches
// (max bank/channel spread), unroll 8 for store MLP.

#define B_DIM   64
#define T_DIM   2000
#define C_DIM   26
#define NCTX    9
#define WINDOW  19
#define ROW_F   (WINDOW * C_DIM)          // 494
#define SLIDE   (ROW_F - C_DIM)           // 468
#define XROW_F  (T_DIM * C_DIM)           // 52000 floats per batch
#define TILE_T  50                         // output rows per block
#define TILE_F4 (TILE_T * ROW_F / 4)       // 6175 float4 per tile
#define NTHREADS 256

__global__ __launch_bounds__(NTHREADS) void overlap_windows_kernel(
    const float* __restrict__ x, float* __restrict__ out)
{
    const int b    = blockIdx.x;          // 0..63  (fast dim: spread batches)
    const int tile = blockIdx.y;          // 0..39
    const int t0   = tile * TILE_T;
    const int tid  = threadIdx.x;

    const float* xb = x + (size_t)b * XROW_F;
    float* tout = out + ((size_t)b * T_DIM + t0) * ROW_F;  // 16B aligned
    const int s0 = (t0 - NCTX) * C_DIM;   // may be negative (tile 0)

    #pragma unroll 8
    for (int i4 = tid; i4 < TILE_F4; i4 += NTHREADS) {
        const int fe = i4 * 4;

        const int trow0 = fe / ROW_F;                 // mul-hi divide
        const int k0    = fe - trow0 * ROW_F;         // 0..492, even
        const int p0    = s0 + fe - trow0 * SLIDE;
        const int trow1 = trow0 + ((k0 + 2 >= ROW_F) ? 1 : 0);
        const int p1    = s0 + (fe + 2) - trow1 * SLIDE;

        float2 a = make_float2(0.0f, 0.0f);
        float2 c = make_float2(0.0f, 0.0f);
        if ((unsigned)p0 < (unsigned)XROW_F)
            a = *reinterpret_cast<const float2*>(xb + p0);
        if ((unsigned)p1 < (unsigned)XROW_F)
            c = *reinterpret_cast<const float2*>(xb + p1);

        __stcs(reinterpret_cast<float4*>(tout + fe),
               make_float4(a.x, a.y, c.x, c.y));
    }
}

extern "C" void kernel_launch(void* const* d_in, const int* in_sizes, int n_in,
                              void* d_out, int out_size)
{
    const float* x = (const float*)d_in[0];
    float* out = (float*)d_out;

    dim3 grid(B_DIM, T_DIM / TILE_T);     // 64 x 40 = 2560 blocks
    overlap_windows_kernel<<<grid, NTHREADS>>>(x, out);
}

// round 10
// speedup vs baseline: 1.2123x; 1.0949x over previous
#include <cuda_runtime.h>

// CreateOverlappingWindows: x (B=64, T=2000, C=26) fp32 ->
// out (B*T, 19*26), N_CONTEXT=9, zero-padded edges.
//
// out row (b,t) = contiguous x slice x[b, t-9 : t+10, :] flattened.
// Direct gather: 2x predicated LDG.64 (L2/L1-resident source) ->
// 1x STG.128 streaming (.cs), flat fully-coalesced stores.
//
// Established: workload is at the HBM write roofline (~253 MB stores per
// replay); five structurally different datapaths measured equivalent.
// This is the best-measured body (R4) with 512-thread blocks / TILE_T=100.
//
// src for flat tile offset fe: trow = fe/494, p = s0 + fe - trow*468,
// valid iff (unsigned)p < 52000.

#define B_DIM   64
#define T_DIM   2000
#define C_DIM   26
#define NCTX    9
#define WINDOW  19
#define ROW_F   (WINDOW * C_DIM)          // 494
#define SLIDE   (ROW_F - C_DIM)           // 468
#define XROW_F  (T_DIM * C_DIM)           // 52000 floats per batch
#define TILE_T  100                        // output rows per block
#define TILE_F4 (TILE_T * ROW_F / 4)       // 12350 float4 per tile
#define NTHREADS 512

__global__ __launch_bounds__(NTHREADS) void overlap_windows_kernel(
    const float* __restrict__ x, float* __restrict__ out)
{
    const int tile = blockIdx.x;          // 0..19
    const int b    = blockIdx.y;          // 0..63
    const int t0   = tile * TILE_T;
    const int tid  = threadIdx.x;

    const float* xb = x + (size_t)b * XROW_F;
    float* tout = out + ((size_t)b * T_DIM + t0) * ROW_F;  // 16B aligned
    const int s0 = (t0 - NCTX) * C_DIM;   // may be negative (tile 0)

    #pragma unroll 4
    for (int i4 = tid; i4 < TILE_F4; i4 += NTHREADS) {
        const int fe = i4 * 4;

        // first float2 half
        const int trow0 = fe / ROW_F;                 // mul-hi divide
        const int k0    = fe - trow0 * ROW_F;         // 0..492, even
        const int p0    = s0 + fe - trow0 * SLIDE;
        // second half: crosses into next output row iff k0+2 >= 494
        const int trow1 = trow0 + ((k0 + 2 >= ROW_F) ? 1 : 0);
        const int p1    = s0 + (fe + 2) - trow1 * SLIDE;

        float2 a = make_float2(0.0f, 0.0f);
        float2 c = make_float2(0.0f, 0.0f);
        if ((unsigned)p0 < (unsigned)XROW_F)
            a = *reinterpret_cast<const float2*>(xb + p0);
        if ((unsigned)p1 < (unsigned)XROW_F)
            c = *reinterpret_cast<const float2*>(xb + p1);

        __stcs(reinterpret_cast<float4*>(tout + fe),
               make_float4(a.x, a.y, c.x, c.y));
    }
}

extern "C" void kernel_launch(void* const* d_in, const int* in_sizes, int n_in,
                              void* d_out, int out_size)
{
    const float* x = (const float*)d_in[0];
    float* out = (float*)d_out;

    dim3 grid(T_DIM / TILE_T, B_DIM);     // 20 x 64 = 1280 blocks
    overlap_windows_kernel<<<grid, NTHREADS>>>(x, out);
}